// round 2
// baseline (speedup 1.0000x reference)
#include <cuda_runtime.h>

// TuckerLinearLayer: y = ((x ⊗in f3,f4,f5) @ core^T) ⊗out f0,f1,f2 + bias
// N=4096, IN=16^3=4096, OUT=16^3=4096, ranks 8 each (R3=512).

#define IN_TOT 4096
#define OUT_TOT 4096
#define R3 512
#define MAX_N 4096

__device__ float g_T1[(size_t)MAX_N * R3];  // 8 MB
__device__ float g_T2[(size_t)MAX_N * R3];  // 8 MB

// ---------------------------------------------------------------------------
// Kernel A: in-side mode contractions.
// t1[n, l,m,nn] = sum_{d,e,f} x[n, d,e,f] f3[d,l] f4[e,m] f5[f,nn]
// One block per sample n. Layouts keep the last rank index contiguous.
// ---------------------------------------------------------------------------
__global__ __launch_bounds__(256) void kA(const float* __restrict__ x,
                                          const float* __restrict__ f3,
                                          const float* __restrict__ f4,
                                          const float* __restrict__ f5) {
    __shared__ __align__(16) float sx[256 * 17];  // x row, stride-17 pad (bank-conflict free)
    __shared__ __align__(16) float u1[2048];      // [de][nn]   de = d*16+e
    __shared__ __align__(16) float u2[1024];      // [d*8+m][nn]
    __shared__ float f3s[128], f4s[128], f5s[128];

    const int t = threadIdx.x;
    const int n = blockIdx.x;

    if (t < 128) { f3s[t] = f3[t]; f4s[t] = f4[t]; f5s[t] = f5[t]; }

    const float4* x4 = reinterpret_cast<const float4*>(x + (size_t)n * IN_TOT);
#pragma unroll
    for (int i = 0; i < 4; i++) {
        int idx4 = t + i * 256;            // 0..1023 (float4 index in row)
        float4 v = x4[idx4];
        int de  = idx4 >> 2;
        int fof = (idx4 & 3) * 4;
        float* dst = &sx[de * 17 + fof];
        dst[0] = v.x; dst[1] = v.y; dst[2] = v.z; dst[3] = v.w;
    }
    __syncthreads();

    // u1[de*8+nn] = sum_f sx[de,f] * f5[f,nn]    (thread = de, 8 accumulators)
    {
        const int de = t;
        float acc[8];
#pragma unroll
        for (int i = 0; i < 8; i++) acc[i] = 0.f;
        const float4* f5v = reinterpret_cast<const float4*>(f5s);
#pragma unroll
        for (int f = 0; f < 16; f++) {
            float xv = sx[de * 17 + f];
            float4 w0 = f5v[f * 2 + 0];
            float4 w1 = f5v[f * 2 + 1];
            acc[0] += xv * w0.x; acc[1] += xv * w0.y;
            acc[2] += xv * w0.z; acc[3] += xv * w0.w;
            acc[4] += xv * w1.x; acc[5] += xv * w1.y;
            acc[6] += xv * w1.z; acc[7] += xv * w1.w;
        }
        float4* u14 = reinterpret_cast<float4*>(u1);
        u14[de * 2 + 0] = make_float4(acc[0], acc[1], acc[2], acc[3]);
        u14[de * 2 + 1] = make_float4(acc[4], acc[5], acc[6], acc[7]);
    }
    __syncthreads();

    // u2[(d*8+m)*8+nn] = sum_e u1[(d*16+e)*8+nn] * f4[e,m]   (thread = d*8+m)
    if (t < 128) {
        const int d = t >> 3, m = t & 7;
        float acc[8];
#pragma unroll
        for (int i = 0; i < 8; i++) acc[i] = 0.f;
        const float4* u14 = reinterpret_cast<const float4*>(u1);
#pragma unroll
        for (int e = 0; e < 16; e++) {
            float fv = f4s[e * 8 + m];
            float4 a = u14[(d * 16 + e) * 2 + 0];
            float4 b = u14[(d * 16 + e) * 2 + 1];
            acc[0] += fv * a.x; acc[1] += fv * a.y;
            acc[2] += fv * a.z; acc[3] += fv * a.w;
            acc[4] += fv * b.x; acc[5] += fv * b.y;
            acc[6] += fv * b.z; acc[7] += fv * b.w;
        }
        float4* u24 = reinterpret_cast<float4*>(u2);
        u24[t * 2 + 0] = make_float4(acc[0], acc[1], acc[2], acc[3]);
        u24[t * 2 + 1] = make_float4(acc[4], acc[5], acc[6], acc[7]);
    }
    __syncthreads();

    // t1[(l*8+m)*8+nn] = sum_d u2[(d*8+m)*8+nn] * f3[d,l]    (thread = l*8+m)
    if (t < 64) {
        const int l = t >> 3, m = t & 7;
        float acc[8];
#pragma unroll
        for (int i = 0; i < 8; i++) acc[i] = 0.f;
        const float4* u24 = reinterpret_cast<const float4*>(u2);
#pragma unroll
        for (int d = 0; d < 16; d++) {
            float fv = f3s[d * 8 + l];
            float4 a = u24[(d * 8 + m) * 2 + 0];
            float4 b = u24[(d * 8 + m) * 2 + 1];
            acc[0] += fv * a.x; acc[1] += fv * a.y;
            acc[2] += fv * a.z; acc[3] += fv * a.w;
            acc[4] += fv * b.x; acc[5] += fv * b.y;
            acc[6] += fv * b.z; acc[7] += fv * b.w;
        }
        float4* out4 = reinterpret_cast<float4*>(g_T1 + (size_t)n * R3);
        out4[t * 2 + 0] = make_float4(acc[0], acc[1], acc[2], acc[3]);
        out4[t * 2 + 1] = make_float4(acc[4], acc[5], acc[6], acc[7]);
    }
}

// ---------------------------------------------------------------------------
// Kernel B: core GEMM. T2[n,o] = sum_k T1[n,k] * core[o*512+k]
// M=4096, N=512, K=512, both operands K-contiguous (NT GEMM).
// 128x128 tile, BK=16, 256 threads, split 8x8 micro-tile per thread.
// ---------------------------------------------------------------------------
#define BM 128
#define BN 128
#define BK 16

__global__ __launch_bounds__(256) void kB(const float* __restrict__ core) {
    __shared__ __align__(16) float As[BK][BM];
    __shared__ __align__(16) float Bs[BK][BN];

    const int t  = threadIdx.x;
    const int bm = blockIdx.y * BM;
    const int bn = blockIdx.x * BN;
    const int tx = t & 15, ty = t >> 4;
    const int lr = t >> 2;            // 0..63  (row within half-tile)
    const int lk = (t & 3) * 4;       // 0,4,8,12

    const float* A = g_T1;
    float acc[8][8];
#pragma unroll
    for (int i = 0; i < 8; i++)
#pragma unroll
        for (int j = 0; j < 8; j++) acc[i][j] = 0.f;

    for (int k0 = 0; k0 < R3; k0 += BK) {
#pragma unroll
        for (int p = 0; p < 2; p++) {
            int r = lr + p * 64;
            float4 va = *reinterpret_cast<const float4*>(&A[(size_t)(bm + r) * R3 + k0 + lk]);
            As[lk + 0][r] = va.x; As[lk + 1][r] = va.y;
            As[lk + 2][r] = va.z; As[lk + 3][r] = va.w;
            float4 vb = *reinterpret_cast<const float4*>(&core[(size_t)(bn + r) * R3 + k0 + lk]);
            Bs[lk + 0][r] = vb.x; Bs[lk + 1][r] = vb.y;
            Bs[lk + 2][r] = vb.z; Bs[lk + 3][r] = vb.w;
        }
        __syncthreads();
#pragma unroll
        for (int kk = 0; kk < BK; kk++) {
            float4 a0 = *reinterpret_cast<const float4*>(&As[kk][ty * 4]);
            float4 a1 = *reinterpret_cast<const float4*>(&As[kk][64 + ty * 4]);
            float4 b0 = *reinterpret_cast<const float4*>(&Bs[kk][tx * 4]);
            float4 b1 = *reinterpret_cast<const float4*>(&Bs[kk][64 + tx * 4]);
            float av[8] = {a0.x, a0.y, a0.z, a0.w, a1.x, a1.y, a1.z, a1.w};
            float bv[8] = {b0.x, b0.y, b0.z, b0.w, b1.x, b1.y, b1.z, b1.w};
#pragma unroll
            for (int i = 0; i < 8; i++)
#pragma unroll
                for (int j = 0; j < 8; j++) acc[i][j] += av[i] * bv[j];
        }
        __syncthreads();
    }

    float* C = g_T2;
#pragma unroll
    for (int i = 0; i < 8; i++) {
        int r = bm + ((i < 4) ? (ty * 4 + i) : (64 + ty * 4 + (i - 4)));
        float4 c0 = make_float4(acc[i][0], acc[i][1], acc[i][2], acc[i][3]);
        float4 c1 = make_float4(acc[i][4], acc[i][5], acc[i][6], acc[i][7]);
        *reinterpret_cast<float4*>(&C[(size_t)r * R3 + bn + tx * 4]) = c0;
        *reinterpret_cast<float4*>(&C[(size_t)r * R3 + bn + 64 + tx * 4]) = c1;
    }
}

// ---------------------------------------------------------------------------
// Kernel C: out-side mode expansion + bias.
// y[n, a,b,c] = sum_{i,j,k} f0[a,i] f1[b,j] f2[c,k] t2[n, i,j,k] + bias[abc]
// ---------------------------------------------------------------------------
__global__ __launch_bounds__(256) void kC(const float* __restrict__ f0,
                                          const float* __restrict__ f1,
                                          const float* __restrict__ f2,
                                          const float* __restrict__ bias,
                                          float* __restrict__ y) {
    __shared__ __align__(16) float t2s[512];   // [i*8+j][k]
    __shared__ __align__(16) float v1[1024];   // [(a*8+j)][k]
    __shared__ __align__(16) float v2[2048];   // [(a*16+b)][k]
    __shared__ float f0s[128], f1s[128], f2s[128];

    const int t = threadIdx.x;
    const int n = blockIdx.x;

    if (t < 128) {
        f0s[t] = f0[t]; f1s[t] = f1[t]; f2s[t] = f2[t];
        reinterpret_cast<float4*>(t2s)[t] =
            reinterpret_cast<const float4*>(g_T2 + (size_t)n * R3)[t];
    }
    __syncthreads();

    // v1[(a*8+j)*8+k] = sum_i f0[a,i] * t2[(i*8+j)*8+k]   (thread = a*8+j)
    if (t < 128) {
        const int a = t >> 3, j = t & 7;
        float acc[8];
#pragma unroll
        for (int i = 0; i < 8; i++) acc[i] = 0.f;
        const float4* t24 = reinterpret_cast<const float4*>(t2s);
#pragma unroll
        for (int i = 0; i < 8; i++) {
            float fv = f0s[a * 8 + i];
            float4 p = t24[(i * 8 + j) * 2 + 0];
            float4 q = t24[(i * 8 + j) * 2 + 1];
            acc[0] += fv * p.x; acc[1] += fv * p.y;
            acc[2] += fv * p.z; acc[3] += fv * p.w;
            acc[4] += fv * q.x; acc[5] += fv * q.y;
            acc[6] += fv * q.z; acc[7] += fv * q.w;
        }
        float4* v14 = reinterpret_cast<float4*>(v1);
        v14[t * 2 + 0] = make_float4(acc[0], acc[1], acc[2], acc[3]);
        v14[t * 2 + 1] = make_float4(acc[4], acc[5], acc[6], acc[7]);
    }
    __syncthreads();

    // v2[(a*16+b)*8+k] = sum_j f1[b,j] * v1[(a*8+j)*8+k]   (thread = a*16+b)
    {
        const int a = t >> 4, b = t & 15;
        float acc[8];
#pragma unroll
        for (int i = 0; i < 8; i++) acc[i] = 0.f;
        const float4* v14 = reinterpret_cast<const float4*>(v1);
#pragma unroll
        for (int j = 0; j < 8; j++) {
            float fv = f1s[b * 8 + j];
            float4 p = v14[(a * 8 + j) * 2 + 0];
            float4 q = v14[(a * 8 + j) * 2 + 1];
            acc[0] += fv * p.x; acc[1] += fv * p.y;
            acc[2] += fv * p.z; acc[3] += fv * p.w;
            acc[4] += fv * q.x; acc[5] += fv * q.y;
            acc[6] += fv * q.z; acc[7] += fv * q.w;
        }
        float4* v24 = reinterpret_cast<float4*>(v2);
        v24[t * 2 + 0] = make_float4(acc[0], acc[1], acc[2], acc[3]);
        v24[t * 2 + 1] = make_float4(acc[4], acc[5], acc[6], acc[7]);
    }
    __syncthreads();

    // y[4s + cc] = sum_k f2[c,k]*v2[ab*8+k] + bias; float4 slot s = t + 256p
    {
        const int c0 = (t & 3) * 4;
        float fr[4][8];
        const float4* f2v = reinterpret_cast<const float4*>(f2s);
#pragma unroll
        for (int cc = 0; cc < 4; cc++) {
            float4 p = f2v[(c0 + cc) * 2 + 0];
            float4 q = f2v[(c0 + cc) * 2 + 1];
            fr[cc][0] = p.x; fr[cc][1] = p.y; fr[cc][2] = p.z; fr[cc][3] = p.w;
            fr[cc][4] = q.x; fr[cc][5] = q.y; fr[cc][6] = q.z; fr[cc][7] = q.w;
        }
        const float4* v24 = reinterpret_cast<const float4*>(v2);
        const float4* bias4 = reinterpret_cast<const float4*>(bias);
        float4* y4 = reinterpret_cast<float4*>(y) + (size_t)n * (OUT_TOT / 4);
#pragma unroll
        for (int p = 0; p < 4; p++) {
            int s  = t + 256 * p;        // float4 slot in output row
            int ab = s >> 2;
            float4 va = v24[ab * 2 + 0];
            float4 vb = v24[ab * 2 + 1];
            float vr[8] = {va.x, va.y, va.z, va.w, vb.x, vb.y, vb.z, vb.w};
            float out[4];
#pragma unroll
            for (int cc = 0; cc < 4; cc++) {
                float s0 = 0.f;
#pragma unroll
                for (int k = 0; k < 8; k++) s0 += fr[cc][k] * vr[k];
                out[cc] = s0;
            }
            float4 bz = __ldg(&bias4[s]);
            y4[s] = make_float4(out[0] + bz.x, out[1] + bz.y,
                                out[2] + bz.z, out[3] + bz.w);
        }
    }
}

// ---------------------------------------------------------------------------
extern "C" void kernel_launch(void* const* d_in, const int* in_sizes, int n_in,
                              void* d_out, int out_size) {
    const float* x    = (const float*)d_in[0];
    const float* core = (const float*)d_in[1];
    const float* f0   = (const float*)d_in[2];
    const float* f1   = (const float*)d_in[3];
    const float* f2   = (const float*)d_in[4];
    const float* f3   = (const float*)d_in[5];
    const float* f4   = (const float*)d_in[6];
    const float* f5   = (const float*)d_in[7];
    const float* bias = (const float*)d_in[8];
    float* y = (float*)d_out;

    const int N = in_sizes[0] / IN_TOT;   // 4096

    kA<<<N, 256>>>(x, f3, f4, f5);
    dim3 gB(R3 / BN, N / BM);
    kB<<<gB, 256>>>(core);
    kC<<<N, 256>>>(f0, f1, f2, bias, y);
}

// round 5
// speedup vs baseline: 1.2359x; 1.2359x over previous
#include <cuda_runtime.h>
#include <cstdint>

// TuckerLinearLayer: y = ((x ⊗in f3,f4,f5) @ core^T) ⊗out f0,f1,f2 + bias
// N=4096, IN=16^3=4096, OUT=16^3=4096, ranks 8 each (R3=512).
// kB: warp-level mma.sync tf32 GEMM (3xTF32 hi/lo split, fp32 accuracy).
// NOTE: harness targets compute_103 (no 'a') -> tcgen05 unavailable; mma.sync is.

#define IN_TOT 4096
#define OUT_TOT 4096
#define R3 512
#define MAX_N 4096

__device__ float g_T1[(size_t)MAX_N * R3];  // 8 MB
__device__ float g_T2[(size_t)MAX_N * R3];  // 8 MB

__device__ __forceinline__ float tf32_rna(float a) {
    float r; asm("cvt.rna.tf32.f32 %0, %1;" : "=f"(r) : "f"(a)); return r;
}

// m16n8k8 tf32 MMA, D += A*B. Operands are pre-rounded tf32 values in f32 regs.
__device__ __forceinline__ void mma_tf32(float* d, const float* a, const float* b) {
    asm volatile(
        "mma.sync.aligned.m16n8k8.row.col.f32.tf32.tf32.f32 "
        "{%0,%1,%2,%3}, {%4,%5,%6,%7}, {%8,%9}, {%0,%1,%2,%3};"
        : "+f"(d[0]), "+f"(d[1]), "+f"(d[2]), "+f"(d[3])
        : "r"(__float_as_uint(a[0])), "r"(__float_as_uint(a[1])),
          "r"(__float_as_uint(a[2])), "r"(__float_as_uint(a[3])),
          "r"(__float_as_uint(b[0])), "r"(__float_as_uint(b[1])));
}

// ---------------------------------------------------------------------------
// Kernel A: in-side mode contractions (x row held in registers).
// t1[n, l,m,nn] = sum_{d,e,f} x[n, d,e,f] f3[d,l] f4[e,m] f5[f,nn]
// ---------------------------------------------------------------------------
__global__ __launch_bounds__(256) void kA(const float* __restrict__ x,
                                          const float* __restrict__ f3,
                                          const float* __restrict__ f4,
                                          const float* __restrict__ f5) {
    __shared__ __align__(16) float u1[2048];      // [de][nn]
    __shared__ __align__(16) float u2[1024];      // [d*8+m][nn]
    __shared__ float f3s[128], f4s[128], f5s[128];

    const int t = threadIdx.x;
    const int n = blockIdx.x;

    if (t < 128) { f3s[t] = f3[t]; f4s[t] = f4[t]; f5s[t] = f5[t]; }

    float xv[16];
    {
        const float4* x4 = reinterpret_cast<const float4*>(x + (size_t)n * IN_TOT + t * 16);
#pragma unroll
        for (int q = 0; q < 4; q++) {
            float4 v = x4[q];
            xv[q * 4 + 0] = v.x; xv[q * 4 + 1] = v.y;
            xv[q * 4 + 2] = v.z; xv[q * 4 + 3] = v.w;
        }
    }
    __syncthreads();

    // u1[de*8+nn] = sum_f xv[f] * f5[f,nn]
    {
        float acc[8];
#pragma unroll
        for (int i = 0; i < 8; i++) acc[i] = 0.f;
        const float4* f5v = reinterpret_cast<const float4*>(f5s);
#pragma unroll
        for (int f = 0; f < 16; f++) {
            float v = xv[f];
            float4 w0 = f5v[f * 2 + 0];
            float4 w1 = f5v[f * 2 + 1];
            acc[0] += v * w0.x; acc[1] += v * w0.y;
            acc[2] += v * w0.z; acc[3] += v * w0.w;
            acc[4] += v * w1.x; acc[5] += v * w1.y;
            acc[6] += v * w1.z; acc[7] += v * w1.w;
        }
        float4* u14 = reinterpret_cast<float4*>(u1);
        u14[t * 2 + 0] = make_float4(acc[0], acc[1], acc[2], acc[3]);
        u14[t * 2 + 1] = make_float4(acc[4], acc[5], acc[6], acc[7]);
    }
    __syncthreads();

    // u2[(d*8+m)*8+nn] = sum_e u1[(d*16+e)*8+nn] * f4[e,m]
    if (t < 128) {
        const int d = t >> 3, m = t & 7;
        float acc[8];
#pragma unroll
        for (int i = 0; i < 8; i++) acc[i] = 0.f;
        const float4* u14 = reinterpret_cast<const float4*>(u1);
#pragma unroll
        for (int e = 0; e < 16; e++) {
            float fv = f4s[e * 8 + m];
            float4 a = u14[(d * 16 + e) * 2 + 0];
            float4 b = u14[(d * 16 + e) * 2 + 1];
            acc[0] += fv * a.x; acc[1] += fv * a.y;
            acc[2] += fv * a.z; acc[3] += fv * a.w;
            acc[4] += fv * b.x; acc[5] += fv * b.y;
            acc[6] += fv * b.z; acc[7] += fv * b.w;
        }
        float4* u24 = reinterpret_cast<float4*>(u2);
        u24[t * 2 + 0] = make_float4(acc[0], acc[1], acc[2], acc[3]);
        u24[t * 2 + 1] = make_float4(acc[4], acc[5], acc[6], acc[7]);
    }
    __syncthreads();

    // t1[(l*8+m)*8+nn] = sum_d u2[(d*8+m)*8+nn] * f3[d,l]
    if (t < 64) {
        const int l = t >> 3, m = t & 7;
        float acc[8];
#pragma unroll
        for (int i = 0; i < 8; i++) acc[i] = 0.f;
        const float4* u24 = reinterpret_cast<const float4*>(u2);
#pragma unroll
        for (int d = 0; d < 16; d++) {
            float fv = f3s[d * 8 + l];
            float4 a = u24[(d * 8 + m) * 2 + 0];
            float4 b = u24[(d * 8 + m) * 2 + 1];
            acc[0] += fv * a.x; acc[1] += fv * a.y;
            acc[2] += fv * a.z; acc[3] += fv * a.w;
            acc[4] += fv * b.x; acc[5] += fv * b.y;
            acc[6] += fv * b.z; acc[7] += fv * b.w;
        }
        float4* out4 = reinterpret_cast<float4*>(g_T1 + (size_t)n * R3);
        out4[t * 2 + 0] = make_float4(acc[0], acc[1], acc[2], acc[3]);
        out4[t * 2 + 1] = make_float4(acc[4], acc[5], acc[6], acc[7]);
    }
}

// ---------------------------------------------------------------------------
// Kernel B: T2[m,o] = sum_k T1[m,k] * core[o,k].  M=4096, N=512, K=512.
// mma.sync m16n8k8 tf32 with hi/lo compensation: D = Ah*Bh + Al*Bh + Ah*Bl.
// CTA tile 128x128, BK=32, 256 threads (warp grid 4m x 2n, warp tile 32x64).
// Double-buffered smem (pad stride 36 floats -> conflict-free fragment LDS).
// Grid = 32 x 4 = 128 CTAs (single wave on 148 SMs).
// ---------------------------------------------------------------------------
#define KB_BM 128
#define KB_BN 128
#define KB_BK 32
#define KB_STAGES (R3 / KB_BK)            // 16
#define KB_LDS 36                          // padded row stride (floats)
#define KB_BUF (KB_BM * KB_LDS)            // floats per tile buffer (4608)
#define KB_SMEM_FLOATS (2 * 4 * KB_BUF)    // 2 stages x {Ah,Al,Bh,Bl}
#define KB_SMEM_BYTES (KB_SMEM_FLOATS * 4) // 147456

extern __shared__ __align__(16) float kb_smem[];

__global__ __launch_bounds__(256, 1) void kB(const float* __restrict__ core) {
    const int t = threadIdx.x;
    const int bm = blockIdx.y * KB_BM;
    const int bn = blockIdx.x * KB_BN;

    const int lane = t & 31;
    const int warp = t >> 5;
    const int quad = lane >> 2;        // 0..7
    const int tig  = lane & 3;         // 0..3
    const int wm = (warp & 3) * 32;    // warp m-offset in CTA tile
    const int wn = (warp >> 2) * 64;   // warp n-offset in CTA tile

    // Accumulators: 2 m-frags x 8 n-frags x 4 regs
    float acc[2][8][4];
#pragma unroll
    for (int i = 0; i < 2; i++)
#pragma unroll
        for (int j = 0; j < 8; j++)
#pragma unroll
            for (int q = 0; q < 4; q++) acc[i][j][q] = 0.f;

    // Per-thread load coordinates (4 float4 per tile per thread)
    // idx = t + 256*i : row = idx>>3 (0..127), c4 = idx&7 (float4 col)
    float4 pfA[4], pfB[4];

    // Prologue: load stage 0
    {
#pragma unroll
        for (int i = 0; i < 4; i++) {
            int idx = t + 256 * i;
            int r = idx >> 3, c4 = idx & 7;
            pfA[i] = *reinterpret_cast<const float4*>(&g_T1[(size_t)(bm + r) * R3 + c4 * 4]);
            pfB[i] = *reinterpret_cast<const float4*>(&core[(size_t)(bn + r) * R3 + c4 * 4]);
        }
    }

    for (int s = 0; s < KB_STAGES; s++) {
        const int b = s & 1;
        float* Ah = kb_smem + b * (4 * KB_BUF);
        float* Al = Ah + KB_BUF;
        float* Bh = Ah + 2 * KB_BUF;
        float* Bl = Ah + 3 * KB_BUF;

        // Store prefetched stage s (convert to hi/lo tf32)
#pragma unroll
        for (int i = 0; i < 4; i++) {
            int idx = t + 256 * i;
            int r = idx >> 3, c4 = idx & 7;
            int so = r * KB_LDS + c4 * 4;
            float4 v = pfA[i];
            float4 h, l;
            h.x = tf32_rna(v.x); l.x = tf32_rna(v.x - h.x);
            h.y = tf32_rna(v.y); l.y = tf32_rna(v.y - h.y);
            h.z = tf32_rna(v.z); l.z = tf32_rna(v.z - h.z);
            h.w = tf32_rna(v.w); l.w = tf32_rna(v.w - h.w);
            *reinterpret_cast<float4*>(&Ah[so]) = h;
            *reinterpret_cast<float4*>(&Al[so]) = l;
            v = pfB[i];
            h.x = tf32_rna(v.x); l.x = tf32_rna(v.x - h.x);
            h.y = tf32_rna(v.y); l.y = tf32_rna(v.y - h.y);
            h.z = tf32_rna(v.z); l.z = tf32_rna(v.z - h.z);
            h.w = tf32_rna(v.w); l.w = tf32_rna(v.w - h.w);
            *reinterpret_cast<float4*>(&Bh[so]) = h;
            *reinterpret_cast<float4*>(&Bl[so]) = l;
        }
        __syncthreads();

        // Prefetch stage s+1 (LDG latency hidden under compute)
        if (s + 1 < KB_STAGES) {
            int k0 = (s + 1) * KB_BK;
#pragma unroll
            for (int i = 0; i < 4; i++) {
                int idx = t + 256 * i;
                int r = idx >> 3, c4 = idx & 7;
                pfA[i] = *reinterpret_cast<const float4*>(&g_T1[(size_t)(bm + r) * R3 + k0 + c4 * 4]);
                pfB[i] = *reinterpret_cast<const float4*>(&core[(size_t)(bn + r) * R3 + k0 + c4 * 4]);
            }
        }

        // Compute: 3 passes (Ah*Bh, Al*Bh, Ah*Bl) x 4 k8-steps
#pragma unroll
        for (int p = 0; p < 3; p++) {
            const float* Ab = (p == 1) ? Al : Ah;
            const float* Bb = (p == 2) ? Bl : Bh;
#pragma unroll
            for (int kk = 0; kk < KB_BK; kk += 8) {
                float afr[2][4];
#pragma unroll
                for (int i = 0; i < 2; i++) {
                    int r = wm + 16 * i + quad;
                    afr[i][0] = Ab[r * KB_LDS + kk + tig];
                    afr[i][1] = Ab[(r + 8) * KB_LDS + kk + tig];
                    afr[i][2] = Ab[r * KB_LDS + kk + tig + 4];
                    afr[i][3] = Ab[(r + 8) * KB_LDS + kk + tig + 4];
                }
#pragma unroll
                for (int j = 0; j < 8; j++) {
                    int nc = wn + 8 * j + quad;
                    float bfr[2];
                    bfr[0] = Bb[nc * KB_LDS + kk + tig];
                    bfr[1] = Bb[nc * KB_LDS + kk + tig + 4];
                    mma_tf32(acc[0][j], afr[0], bfr);
                    mma_tf32(acc[1][j], afr[1], bfr);
                }
            }
        }
        __syncthreads();
    }

    // Epilogue: write accumulators to g_T2 (float2 per frag half-row).
#pragma unroll
    for (int i = 0; i < 2; i++) {
        int r0 = bm + wm + 16 * i + quad;
#pragma unroll
        for (int j = 0; j < 8; j++) {
            int c = bn + wn + 8 * j + 2 * tig;
            *reinterpret_cast<float2*>(&g_T2[(size_t)r0 * R3 + c]) =
                make_float2(acc[i][j][0], acc[i][j][1]);
            *reinterpret_cast<float2*>(&g_T2[(size_t)(r0 + 8) * R3 + c]) =
                make_float2(acc[i][j][2], acc[i][j][3]);
        }
    }
}

// ---------------------------------------------------------------------------
// Kernel C: out-side mode expansion + bias.
// ---------------------------------------------------------------------------
__global__ __launch_bounds__(256) void kC(const float* __restrict__ f0,
                                          const float* __restrict__ f1,
                                          const float* __restrict__ f2,
                                          const float* __restrict__ bias,
                                          float* __restrict__ y) {
    __shared__ __align__(16) float t2s[512];
    __shared__ __align__(16) float v1[1024];
    __shared__ __align__(16) float v2[2048];
    __shared__ float f0s[128], f1s[128], f2s[128];

    const int t = threadIdx.x;
    const int n = blockIdx.x;

    if (t < 128) {
        f0s[t] = f0[t]; f1s[t] = f1[t]; f2s[t] = f2[t];
        reinterpret_cast<float4*>(t2s)[t] =
            reinterpret_cast<const float4*>(g_T2 + (size_t)n * R3)[t];
    }
    __syncthreads();

    if (t < 128) {
        const int a = t >> 3, j = t & 7;
        float acc[8];
#pragma unroll
        for (int i = 0; i < 8; i++) acc[i] = 0.f;
        const float4* t24 = reinterpret_cast<const float4*>(t2s);
#pragma unroll
        for (int i = 0; i < 8; i++) {
            float fv = f0s[a * 8 + i];
            float4 p = t24[(i * 8 + j) * 2 + 0];
            float4 q = t24[(i * 8 + j) * 2 + 1];
            acc[0] += fv * p.x; acc[1] += fv * p.y;
            acc[2] += fv * p.z; acc[3] += fv * p.w;
            acc[4] += fv * q.x; acc[5] += fv * q.y;
            acc[6] += fv * q.z; acc[7] += fv * q.w;
        }
        float4* v14 = reinterpret_cast<float4*>(v1);
        v14[t * 2 + 0] = make_float4(acc[0], acc[1], acc[2], acc[3]);
        v14[t * 2 + 1] = make_float4(acc[4], acc[5], acc[6], acc[7]);
    }
    __syncthreads();

    {
        const int a = t >> 4, b = t & 15;
        float acc[8];
#pragma unroll
        for (int i = 0; i < 8; i++) acc[i] = 0.f;
        const float4* v14 = reinterpret_cast<const float4*>(v1);
#pragma unroll
        for (int j = 0; j < 8; j++) {
            float fv = f1s[b * 8 + j];
            float4 p = v14[(a * 8 + j) * 2 + 0];
            float4 q = v14[(a * 8 + j) * 2 + 1];
            acc[0] += fv * p.x; acc[1] += fv * p.y;
            acc[2] += fv * p.z; acc[3] += fv * p.w;
            acc[4] += fv * q.x; acc[5] += fv * q.y;
            acc[6] += fv * q.z; acc[7] += fv * q.w;
        }
        float4* v24 = reinterpret_cast<float4*>(v2);
        v24[t * 2 + 0] = make_float4(acc[0], acc[1], acc[2], acc[3]);
        v24[t * 2 + 1] = make_float4(acc[4], acc[5], acc[6], acc[7]);
    }
    __syncthreads();

    {
        const int c0 = (t & 3) * 4;
        float fr[4][8];
        const float4* f2v = reinterpret_cast<const float4*>(f2s);
#pragma unroll
        for (int cc = 0; cc < 4; cc++) {
            float4 p = f2v[(c0 + cc) * 2 + 0];
            float4 q = f2v[(c0 + cc) * 2 + 1];
            fr[cc][0] = p.x; fr[cc][1] = p.y; fr[cc][2] = p.z; fr[cc][3] = p.w;
            fr[cc][4] = q.x; fr[cc][5] = q.y; fr[cc][6] = q.z; fr[cc][7] = q.w;
        }
        const float4* v24 = reinterpret_cast<const float4*>(v2);
        const float4* bias4 = reinterpret_cast<const float4*>(bias);
        float4* y4 = reinterpret_cast<float4*>(y) + (size_t)n * (OUT_TOT / 4);
#pragma unroll
        for (int p = 0; p < 4; p++) {
            int s = t + 256 * p;
            int ab = s >> 2;
            float4 va = v24[ab * 2 + 0];
            float4 vb = v24[ab * 2 + 1];
            float vr[8] = {va.x, va.y, va.z, va.w, vb.x, vb.y, vb.z, vb.w};
            float out[4];
#pragma unroll
            for (int cc = 0; cc < 4; cc++) {
                float s0 = 0.f;
#pragma unroll
                for (int k = 0; k < 8; k++) s0 += fr[cc][k] * vr[k];
                out[cc] = s0;
            }
            float4 bz = __ldg(&bias4[s]);
            y4[s] = make_float4(out[0] + bz.x, out[1] + bz.y,
                                out[2] + bz.z, out[3] + bz.w);
        }
    }
}

// ---------------------------------------------------------------------------
extern "C" void kernel_launch(void* const* d_in, const int* in_sizes, int n_in,
                              void* d_out, int out_size) {
    const float* x    = (const float*)d_in[0];
    const float* core = (const float*)d_in[1];
    const float* f0   = (const float*)d_in[2];
    const float* f1   = (const float*)d_in[3];
    const float* f2   = (const float*)d_in[4];
    const float* f3   = (const float*)d_in[5];
    const float* f4   = (const float*)d_in[6];
    const float* f5   = (const float*)d_in[7];
    const float* bias = (const float*)d_in[8];
    float* y = (float*)d_out;

    const int N = in_sizes[0] / IN_TOT;   // 4096

    static bool attr_set = false;
    if (!attr_set) {
        cudaFuncSetAttribute(kB, cudaFuncAttributeMaxDynamicSharedMemorySize, KB_SMEM_BYTES);
        attr_set = true;
    }

    kA<<<N, 256>>>(x, f3, f4, f5);
    dim3 gB(R3 / KB_BN, N / KB_BM);       // (4, 32)
    kB<<<gB, 256, KB_SMEM_BYTES>>>(core);
    kC<<<N, 256>>>(f0, f1, f2, bias, y);
}